// round 2
// baseline (speedup 1.0000x reference)
#include <cuda_runtime.h>
#include <cstdint>

#define BSZ 4
#define NN  512
#define DD  128
#define ROWS (BSZ * NN)   // 2048

// ---------------- scratch (no allocations allowed) ----------------
__device__ float g_q [BSZ * NN * DD];                 // sigmoid(x Wq^T + bq)
__device__ float g_Ek[BSZ * NN * DD];                 // exp(x Wk^T + bk)
__device__ float g_V [BSZ * NN * DD];                 // x Wv^T + bv
__device__ unsigned long long g_P2[NN * NN];          // (exp(pb), exp(pb)) packed pairs

// packed f32x2 FMA: d.lo += a.lo*b.lo ; d.hi += a.hi*b.hi
__device__ __forceinline__ void ffma2(unsigned long long& d,
                                      unsigned long long a,
                                      unsigned long long b) {
    asm("fma.rn.f32x2 %0, %1, %2, %0;" : "+l"(d) : "l"(a), "l"(b));
}

__device__ __forceinline__ unsigned long long dup_f32(float f) {
    unsigned int u = __float_as_uint(f);
    return ((unsigned long long)u << 32) | (unsigned long long)u;
}

// ---------------- kernel 1: P = exp(pos_bias), duplicated-pair packed ----------------
__global__ __launch_bounds__(256) void exp_pb_kernel(const float* __restrict__ pb) {
    int i = blockIdx.x * 256 + threadIdx.x;   // grid exactly covers NN*NN
    g_P2[i] = dup_f32(__expf(pb[i]));
}

// ---------------- kernel 2: the three projections ----------------
// Out[2048,128] = act(X[2048,128] @ W^T + b). blockIdx.y selects projection.
// Tile: 64 rows x 128 cols, K-tile 32. 256 threads: tx=tid&31 -> cols tx*4..+3,
// ty=tid>>5 -> rows ty*8..+7 (one warp per ty => smem A reads are broadcasts).
__global__ __launch_bounds__(256) void proj_kernel(
    const float* __restrict__ X,
    const float* __restrict__ Wq, const float* __restrict__ bq,
    const float* __restrict__ Wk, const float* __restrict__ bk,
    const float* __restrict__ Wv, const float* __restrict__ bv)
{
    __shared__ unsigned long long Xs2[64][33];          // (x,x) pairs, 16.9 KB
    __shared__ __align__(16) float Ws[32][132];         // W^T tile, 16.9 KB (row stride 528B, 16B-aligned)

    const int p   = blockIdx.y;
    const float* W    = (p == 0) ? Wq : (p == 1) ? Wk : Wv;
    const float* bias = (p == 0) ? bq : (p == 1) ? bk : bv;
    float*       Out  = (p == 0) ? g_q : (p == 1) ? g_Ek : g_V;

    const int r0  = blockIdx.x * 64;
    const int tid = threadIdx.x;
    const int tx  = tid & 31;
    const int ty  = tid >> 5;

    unsigned long long acc[8][2] = {};   // 8 rows x (2 col-pairs) = 8x4 fp32

    for (int kk = 0; kk < DD; kk += 32) {
        // A tile: X rows r0..r0+63, cols kk..kk+31, duplicated pairs
        #pragma unroll
        for (int l = 0; l < 8; l++) {
            int idx = tid + l * 256;
            int row = idx >> 5, col = idx & 31;
            Xs2[row][col] = dup_f32(X[(r0 + row) * DD + kk + col]);
        }
        // B tile: Ws[k][e] = W[e][kk+k]  (coalesced global reads; ~4-way STS conflict, negligible)
        #pragma unroll
        for (int l = 0; l < 16; l++) {
            int idx = tid + l * 256;
            int e = idx >> 5, k = idx & 31;
            Ws[k][e] = W[e * DD + kk + k];
        }
        __syncthreads();

        #pragma unroll
        for (int k = 0; k < 32; k++) {
            ulonglong2 bb = *(const ulonglong2*)&Ws[k][tx * 4];   // cols (4tx,4tx+1),(4tx+2,4tx+3)
            #pragma unroll
            for (int i = 0; i < 8; i++) {
                unsigned long long a2 = Xs2[ty * 8 + i][k];       // warp-broadcast
                ffma2(acc[i][0], a2, bb.x);
                ffma2(acc[i][1], a2, bb.y);
            }
        }
        __syncthreads();
    }

    // epilogue: + bias, activation, float4 store
    const float4 bv4 = *(const float4*)&bias[tx * 4];
    #pragma unroll
    for (int i = 0; i < 8; i++) {
        int r = r0 + ty * 8 + i;
        float4 o;
        o.x = __uint_as_float((unsigned)(acc[i][0]       )) + bv4.x;
        o.y = __uint_as_float((unsigned)(acc[i][0] >> 32)) + bv4.y;
        o.z = __uint_as_float((unsigned)(acc[i][1]       )) + bv4.z;
        o.w = __uint_as_float((unsigned)(acc[i][1] >> 32)) + bv4.w;
        if (p == 0) {        // sigmoid
            o.x = 1.f / (1.f + __expf(-o.x));
            o.y = 1.f / (1.f + __expf(-o.y));
            o.z = 1.f / (1.f + __expf(-o.z));
            o.w = 1.f / (1.f + __expf(-o.w));
        } else if (p == 1) { // exp(k)
            o.x = __expf(o.x); o.y = __expf(o.y);
            o.z = __expf(o.z); o.w = __expf(o.w);
        }
        *(float4*)&Out[r * DD + tx * 4] = o;
    }
}

// ---------------- kernel 3: C[b] = P @ M[b], fused epilogue out = q*num/den ----------------
// M[b][j][2d]   = Ek[b,j,d]*V[b,j,d]   (num component)
// M[b][j][2d+1] = Ek[b,j,d]            (den component)
// Tile 64 t-rows x 64 cols (=32 d pairs), K-tile 32 over N=512.
// 256 threads: tx=tid&15 -> cols 4tx..4tx+3 (2 d-pairs), ty=tid>>4 -> rows 4ty..4ty+3.
__global__ __launch_bounds__(256) void aft_gemm_kernel(float* __restrict__ out) {
    __shared__ unsigned long long As2[64][33];          // (P,P) pairs, 16.9 KB
    __shared__ __align__(16) float Bs[32][68];          // 8.7 KB (row stride 272B, 16B-aligned)

    const int b   = blockIdx.z;
    const int t0  = blockIdx.x * 64;
    const int c0  = blockIdx.y * 64;   // even
    const int tid = threadIdx.x;
    const int tx  = tid & 15;
    const int ty  = tid >> 4;

    const float* Ek = g_Ek + b * NN * DD;
    const float* V  = g_V  + b * NN * DD;

    unsigned long long acc[4][2] = {};   // rows x pairs; lo=num, hi=den

    for (int kk = 0; kk < NN; kk += 32) {
        // A tile: pre-packed pairs, plain 64-bit coalesced loads
        #pragma unroll
        for (int l = 0; l < 8; l++) {
            int idx = tid + l * 256;
            int row = idx >> 5, col = idx & 31;
            As2[row][col] = g_P2[(t0 + row) * NN + kk + col];
        }
        // B tile: interleave (Ek*V, Ek) on the fly
        #pragma unroll
        for (int l = 0; l < 8; l++) {
            int idx  = tid + l * 256;
            int jrow = idx >> 6, c = idx & 63;
            int j  = kk + jrow;
            int cg = c0 + c;
            int d  = cg >> 1;
            float ek = Ek[j * DD + d];
            Bs[jrow][c] = (cg & 1) ? ek : ek * V[j * DD + d];
        }
        __syncthreads();

        #pragma unroll
        for (int k = 0; k < 32; k++) {
            ulonglong2 bb = *(const ulonglong2*)&Bs[k][tx * 4];  // (num0,den0),(num1,den1)
            #pragma unroll
            for (int i = 0; i < 4; i++) {
                unsigned long long a2 = As2[ty * 4 + i][k];
                ffma2(acc[i][0], a2, bb.x);
                ffma2(acc[i][1], a2, bb.y);
            }
        }
        __syncthreads();
    }

    // fused epilogue
    const float* q = g_q + b * NN * DD;
    const int d0 = (c0 >> 1) + tx * 2;   // even -> 8B-aligned float2
    #pragma unroll
    for (int i = 0; i < 4; i++) {
        int t = t0 + ty * 4 + i;
        float num0 = __uint_as_float((unsigned)(acc[i][0]       ));
        float den0 = __uint_as_float((unsigned)(acc[i][0] >> 32));
        float num1 = __uint_as_float((unsigned)(acc[i][1]       ));
        float den1 = __uint_as_float((unsigned)(acc[i][1] >> 32));
        float2 qv = *(const float2*)&q[t * DD + d0];
        float2 o;
        o.x = qv.x * (num0 / den0);
        o.y = qv.y * (num1 / den1);
        *(float2*)&out[(b * NN + t) * DD + d0] = o;
    }
}

// ---------------- launch ----------------
extern "C" void kernel_launch(void* const* d_in, const int* in_sizes, int n_in,
                              void* d_out, int out_size) {
    const float* x  = (const float*)d_in[0];
    const float* Wq = (const float*)d_in[1];
    const float* bq = (const float*)d_in[2];
    const float* Wk = (const float*)d_in[3];
    const float* bk = (const float*)d_in[4];
    const float* Wv = (const float*)d_in[5];
    const float* bv = (const float*)d_in[6];
    const float* pb = (const float*)d_in[7];
    float* out = (float*)d_out;

    exp_pb_kernel<<<(NN * NN) / 256, 256>>>(pb);
    proj_kernel<<<dim3(ROWS / 64, 3), 256>>>(x, Wq, bq, Wk, bk, Wv, bv);
    aft_gemm_kernel<<<dim3(NN / 64, 4, BSZ), 256>>>(out);
}

// round 3
// speedup vs baseline: 1.2723x; 1.2723x over previous
#include <cuda_runtime.h>
#include <cstdint>

#define BSZ 4
#define NN  512
#define DD  128

// ---------------- scratch (no allocations allowed) ----------------
__device__ __align__(16) float g_q [BSZ * NN * DD];
__device__ __align__(16) float g_Ek[BSZ * NN * DD];
__device__ __align__(16) float g_V [BSZ * NN * DD];
__device__ __align__(16) unsigned long long g_P2[NN * NN];   // (expP, expP) pairs

// packed f32x2 FMA: d.lo += a.lo*b.lo ; d.hi += a.hi*b.hi
__device__ __forceinline__ void ffma2(unsigned long long& d,
                                      unsigned long long a,
                                      unsigned long long b) {
    asm("fma.rn.f32x2 %0, %1, %2, %0;" : "+l"(d) : "l"(a), "l"(b));
}
__device__ __forceinline__ unsigned long long dup_f32(float f) {
    unsigned int u = __float_as_uint(f);
    return ((unsigned long long)u << 32) | (unsigned long long)u;
}
__device__ __forceinline__ float lo_f(unsigned long long u) { return __uint_as_float((unsigned)u); }
__device__ __forceinline__ float hi_f(unsigned long long u) { return __uint_as_float((unsigned)(u >> 32)); }

// =============== kernel 1: fused projections (blocks 0..95) + exp(pos_bias) (96..159) ===============
// proj: Out[2048,128] = act(X @ W^T + b); tile 64 rows x 128 cols, K-tile 32, 256 thr.
__global__ __launch_bounds__(256) void prep_kernel(
    const float* __restrict__ X,
    const float* __restrict__ Wq, const float* __restrict__ bq,
    const float* __restrict__ Wk, const float* __restrict__ bk,
    const float* __restrict__ Wv, const float* __restrict__ bv,
    const float* __restrict__ pb)
{
    const int tid = threadIdx.x;
    const int bx  = blockIdx.x;

    if (bx >= 96) {   // ---- exp(pos_bias): 64 blocks x 4096 elems, 16/thread ----
        const int base = (bx - 96) * 4096;
        #pragma unroll
        for (int l = 0; l < 4; l++) {
            int i = base + l * 1024 + tid * 4;
            float4 v = *(const float4*)&pb[i];
            ulonglong2 o0, o1;
            o0.x = dup_f32(__expf(v.x)); o0.y = dup_f32(__expf(v.y));
            o1.x = dup_f32(__expf(v.z)); o1.y = dup_f32(__expf(v.w));
            *(ulonglong2*)&g_P2[i]     = o0;
            *(ulonglong2*)&g_P2[i + 2] = o1;
        }
        return;
    }

    __shared__ __align__(16) unsigned long long Xs2[64][34];   // 17.4 KB, dup pairs, 16B-aligned rows
    __shared__ __align__(16) float Ws[32][132];                // 16.9 KB, W^T tile

    const int p  = bx >> 5;                 // 0..2 : q,k,v
    const int r0 = (bx & 31) * 64;
    const float* W    = (p == 0) ? Wq : (p == 1) ? Wk : Wv;
    const float* bias = (p == 0) ? bq : (p == 1) ? bk : bv;
    float*       Out  = (p == 0) ? g_q : (p == 1) ? g_Ek : g_V;

    const int tx = tid & 31;                // cols 4tx..4tx+3
    const int ty = tid >> 5;                // rows 8ty..8ty+7

    unsigned long long acc[8][2] = {};
    float4 ax[2], wx[4];

    // prefetch K-tile 0
    #pragma unroll
    for (int l = 0; l < 2; l++) {
        int idx = tid + l * 256, row = idx >> 3, c4 = idx & 7;
        ax[l] = *(const float4*)&X[(r0 + row) * DD + 4 * c4];
    }
    #pragma unroll
    for (int l = 0; l < 4; l++) {
        int idx = tid + l * 256, k4 = idx & 7, e = idx >> 3;
        wx[l] = *(const float4*)&W[e * DD + 4 * k4];
    }

    for (int kt = 0; kt < 4; kt++) {
        // stores (regs -> smem)
        #pragma unroll
        for (int l = 0; l < 2; l++) {
            int idx = tid + l * 256, row = idx >> 3, c4 = idx & 7;
            ulonglong2 u0, u1;
            u0.x = dup_f32(ax[l].x); u0.y = dup_f32(ax[l].y);
            u1.x = dup_f32(ax[l].z); u1.y = dup_f32(ax[l].w);
            *(ulonglong2*)&Xs2[row][4 * c4]     = u0;
            *(ulonglong2*)&Xs2[row][4 * c4 + 2] = u1;
        }
        #pragma unroll
        for (int l = 0; l < 4; l++) {
            int idx = tid + l * 256, k4 = idx & 7, e = idx >> 3;
            Ws[4 * k4 + 0][e] = wx[l].x;
            Ws[4 * k4 + 1][e] = wx[l].y;
            Ws[4 * k4 + 2][e] = wx[l].z;
            Ws[4 * k4 + 3][e] = wx[l].w;
        }
        __syncthreads();

        // prefetch next K-tile while computing this one
        if (kt < 3) {
            int kk = (kt + 1) * 32;
            #pragma unroll
            for (int l = 0; l < 2; l++) {
                int idx = tid + l * 256, row = idx >> 3, c4 = idx & 7;
                ax[l] = *(const float4*)&X[(r0 + row) * DD + kk + 4 * c4];
            }
            #pragma unroll
            for (int l = 0; l < 4; l++) {
                int idx = tid + l * 256, k4 = idx & 7, e = idx >> 3;
                wx[l] = *(const float4*)&W[e * DD + kk + 4 * k4];
            }
        }

        // compute: 2 k-steps per iter, 32 ffma2 per 10 LDS128
        #pragma unroll
        for (int k2 = 0; k2 < 16; k2++) {
            ulonglong2 b0 = *(const ulonglong2*)&Ws[2 * k2][tx * 4];
            ulonglong2 b1 = *(const ulonglong2*)&Ws[2 * k2 + 1][tx * 4];
            #pragma unroll
            for (int i = 0; i < 8; i++) {
                ulonglong2 a2 = *(const ulonglong2*)&Xs2[ty * 8 + i][2 * k2];  // broadcast
                ffma2(acc[i][0], a2.x, b0.x);
                ffma2(acc[i][1], a2.x, b0.y);
                ffma2(acc[i][0], a2.y, b1.x);
                ffma2(acc[i][1], a2.y, b1.y);
            }
        }
        __syncthreads();
    }

    // epilogue: + bias, activation, float4 store
    const float4 bv4 = *(const float4*)&bias[tx * 4];
    #pragma unroll
    for (int i = 0; i < 8; i++) {
        int r = r0 + ty * 8 + i;
        float4 o;
        o.x = lo_f(acc[i][0]) + bv4.x;
        o.y = hi_f(acc[i][0]) + bv4.y;
        o.z = lo_f(acc[i][1]) + bv4.z;
        o.w = hi_f(acc[i][1]) + bv4.w;
        if (p == 0) {
            o.x = 1.f / (1.f + __expf(-o.x));
            o.y = 1.f / (1.f + __expf(-o.y));
            o.z = 1.f / (1.f + __expf(-o.z));
            o.w = 1.f / (1.f + __expf(-o.w));
        } else if (p == 1) {
            o.x = __expf(o.x); o.y = __expf(o.y);
            o.z = __expf(o.z); o.w = __expf(o.w);
        }
        *(float4*)&Out[r * DD + tx * 4] = o;
    }
}

// =============== kernel 2: C[b] = P @ M[b], fused out = q*num/den ===============
// M[b][j][2d] = Ek*V, [2d+1] = Ek. Tile 64 t-rows x 64 interleaved cols, K-tile 32 over N=512.
__global__ __launch_bounds__(256) void aft_kernel(float* __restrict__ out)
{
    __shared__ __align__(16) unsigned long long As2[64][34];   // 17.4 KB (expP pairs)
    __shared__ __align__(16) float Bs[32][68];                 //  8.7 KB

    const int b   = blockIdx.z;
    const int t0  = blockIdx.x * 64;
    const int c0  = blockIdx.y * 64;     // interleaved col tile (even)
    const int d0  = c0 >> 1;             // 32 d's per tile
    const int tid = threadIdx.x;
    const int tx  = tid & 15;            // cols 4tx..4tx+3 (2 d-pairs)
    const int ty  = tid >> 4;            // rows 4ty..4ty+3

    const float* Ek = g_Ek + b * NN * DD;
    const float* V  = g_V  + b * NN * DD;

    unsigned long long acc[4][2] = {};   // lo=num, hi=den
    ulonglong2 pa[4];
    float2 e2[2], v2[2];

    // prefetch K-tile 0
    #pragma unroll
    for (int l = 0; l < 4; l++) {
        int idx = tid + l * 256, row = idx >> 4, k2i = idx & 15;
        pa[l] = *(const ulonglong2*)&g_P2[(t0 + row) * NN + 2 * k2i];
    }
    #pragma unroll
    for (int l = 0; l < 2; l++) {
        int idx = tid + l * 256, jr = idx >> 4, dp = idx & 15;
        e2[l] = *(const float2*)&Ek[jr * DD + d0 + 2 * dp];
        v2[l] = *(const float2*)&V [jr * DD + d0 + 2 * dp];
    }

    for (int kt = 0; kt < 16; kt++) {
        // stores (regs -> smem), build interleaved (Ek*V, Ek)
        #pragma unroll
        for (int l = 0; l < 4; l++) {
            int idx = tid + l * 256, row = idx >> 4, k2i = idx & 15;
            *(ulonglong2*)&As2[row][2 * k2i] = pa[l];
        }
        #pragma unroll
        for (int l = 0; l < 2; l++) {
            int idx = tid + l * 256, jr = idx >> 4, dp = idx & 15;
            float4 w;
            w.x = e2[l].x * v2[l].x; w.y = e2[l].x;
            w.z = e2[l].y * v2[l].y; w.w = e2[l].y;
            *(float4*)&Bs[jr][4 * dp] = w;
        }
        __syncthreads();

        // prefetch next K-tile under the compute
        if (kt < 15) {
            int kk = (kt + 1) * 32;
            #pragma unroll
            for (int l = 0; l < 4; l++) {
                int idx = tid + l * 256, row = idx >> 4, k2i = idx & 15;
                pa[l] = *(const ulonglong2*)&g_P2[(t0 + row) * NN + kk + 2 * k2i];
            }
            #pragma unroll
            for (int l = 0; l < 2; l++) {
                int idx = tid + l * 256, jr = idx >> 4, dp = idx & 15;
                e2[l] = *(const float2*)&Ek[(kk + jr) * DD + d0 + 2 * dp];
                v2[l] = *(const float2*)&V [(kk + jr) * DD + d0 + 2 * dp];
            }
        }

        // compute: 2 k-steps per iter, 16 ffma2 per 6 LDS128 -> ffma2-pipe-bound
        #pragma unroll
        for (int k2 = 0; k2 < 16; k2++) {
            ulonglong2 b0 = *(const ulonglong2*)&Bs[2 * k2][tx * 4];
            ulonglong2 b1 = *(const ulonglong2*)&Bs[2 * k2 + 1][tx * 4];
            #pragma unroll
            for (int i = 0; i < 4; i++) {
                ulonglong2 a2 = *(const ulonglong2*)&As2[ty * 4 + i][2 * k2];  // broadcast
                ffma2(acc[i][0], a2.x, b0.x);
                ffma2(acc[i][1], a2.x, b0.y);
                ffma2(acc[i][0], a2.y, b1.x);
                ffma2(acc[i][1], a2.y, b1.y);
            }
        }
        __syncthreads();
    }

    // fused epilogue: out = q * num / den
    const float* q  = g_q + b * NN * DD;
    const int    dd = d0 + 2 * tx;
    #pragma unroll
    for (int i = 0; i < 4; i++) {
        int t = t0 + ty * 4 + i;
        float num0 = lo_f(acc[i][0]), den0 = hi_f(acc[i][0]);
        float num1 = lo_f(acc[i][1]), den1 = hi_f(acc[i][1]);
        float2 qv = *(const float2*)&q[t * DD + dd];
        float2 o;
        o.x = qv.x * (num0 / den0);
        o.y = qv.y * (num1 / den1);
        *(float2*)&out[(b * NN + t) * DD + dd] = o;
    }
}

// ---------------- launch ----------------
extern "C" void kernel_launch(void* const* d_in, const int* in_sizes, int n_in,
                              void* d_out, int out_size) {
    const float* x  = (const float*)d_in[0];
    const float* Wq = (const float*)d_in[1];
    const float* bq = (const float*)d_in[2];
    const float* Wk = (const float*)d_in[3];
    const float* bk = (const float*)d_in[4];
    const float* Wv = (const float*)d_in[5];
    const float* bv = (const float*)d_in[6];
    const float* pb = (const float*)d_in[7];
    float* out = (float*)d_out;

    prep_kernel<<<160, 256>>>(x, Wq, bq, Wk, bk, Wv, bv, pb);
    aft_kernel<<<dim3(NN / 64, 4, BSZ), 256>>>(out);
}